// round 13
// baseline (speedup 1.0000x reference)
#include <cuda_runtime.h>
#include <cuda_bf16.h>
#include <cuda_fp16.h>
#include <cstdint>

#define F     128      // HID == F_IN
#define H     8        // heads
#define DH    16       // dim per head
#define NMAX  65536
#define EMAX  1000000
#define SCAN_B 1024
#define MAXBLK 64      // max scan blocks (ceil(NMAX/1024))

#define STR   136                       // padded bf16 row stride (272 B)
// CTA tile: 64 rows x 128 cols. A hi/lo: 64*272 each; B hi/lo: 128*272 each.
#define A_HI  0
#define A_LO  (64 * STR * 2)            // 17408
#define B_HI  (2 * 64 * STR * 2)        // 34816
#define B_LO  (B_HI + 128 * STR * 2)    // 69632
#define SMEM_TOT (B_LO + 128 * STR * 2) // 104448  -> 2 CTAs/SM

#define GEMM_GRID 296                   // 2 CTAs/SM x 148 SMs: one resident wave

// ---------------- device scratch (no allocations allowed) ----------------
__device__ __align__(16) float  g_xc[NMAX * F];
__device__ __align__(16) __half g_h16[NMAX * F];     // fp16 projected features
__device__ __align__(16) float  g_asrc[NMAX * H];
__device__ __align__(16) float  g_adst[NMAX * H];
__device__ int   g_cnt[NMAX];
__device__ int   g_excl[NMAX];
__device__ int   g_bsum[MAXBLK];
__device__ int   g_offs[NMAX + 1];
__device__ int   g_cursor[NMAX];
__device__ __align__(16) int2 g_ecomb[EMAX];         // packed (col, ev-bits)
// prepped weights: B^T [n][k] padded to STR, hi/lo bf16, 3 matrices
__device__ __align__(16) __nv_bfloat16 g_Bhi[3 * F * STR];
__device__ __align__(16) __nv_bfloat16 g_Blo[3 * F * STR];

// ---------------- helpers ----------------
__device__ __forceinline__ uint32_t smem_u32(const void* p) {
    uint32_t a;
    asm("{ .reg .u64 t; cvta.to.shared.u64 t, %1; cvt.u32.u64 %0, t; }" : "=r"(a) : "l"(p));
    return a;
}
__device__ __forceinline__ void ldx4(uint32_t* r, uint32_t addr) {
    asm volatile("ldmatrix.sync.aligned.m8n8.x4.shared.b16 {%0,%1,%2,%3}, [%4];"
                 : "=r"(r[0]), "=r"(r[1]), "=r"(r[2]), "=r"(r[3]) : "r"(addr));
}
__device__ __forceinline__ void mma_bf16(float* c, const uint32_t* a, uint32_t b0, uint32_t b1) {
    asm volatile("mma.sync.aligned.m16n8k16.row.col.f32.bf16.bf16.f32 "
                 "{%0,%1,%2,%3}, {%4,%5,%6,%7}, {%8,%9}, {%0,%1,%2,%3};"
                 : "+f"(c[0]), "+f"(c[1]), "+f"(c[2]), "+f"(c[3])
                 : "r"(a[0]), "r"(a[1]), "r"(a[2]), "r"(a[3]), "r"(b0), "r"(b1));
}
__device__ __forceinline__ void cp_async16(uint32_t saddr, const void* gptr) {
    asm volatile("cp.async.cg.shared.global [%0], [%1], 16;" :: "r"(saddr), "l"(gptr) : "memory");
}
#define CP_ASYNC_WAIT_ALL() asm volatile("cp.async.wait_all;" ::: "memory")

// ---------------- weight prep: W[k][n] -> B^T[n][k] padded, hi/lo bf16 ----------------
__global__ void prepB_kernel(const float* __restrict__ encW,
                             const float* __restrict__ Wst) {
    int idx = blockIdx.x * blockDim.x + threadIdx.x;
    if (idx >= 3 * F * STR) return;
    int mat = idx / (F * STR);
    int t = idx % (F * STR);
    int n = t / STR, k = t % STR;
    float w = 0.f;
    if (k < F) {
        if (mat == 0) w = encW[k * F + n];
        else {
            int hh = n >> 4, f = n & 15;
            w = Wst[(mat - 1) * (H * F * DH) + (hh * F + k) * DH + f];
        }
    }
    __nv_bfloat16 hi = __float2bfloat16(w);
    __nv_bfloat16 lo = __float2bfloat16(w - __bfloat162float(hi));
    g_Bhi[idx] = hi;
    g_Blo[idx] = lo;
}

// ---------------- persistent HMMA GEMM: C = A @ W (+bias), fused alpha ----------------
// grid = GEMM_GRID; each CTA stages B hi/lo ONCE (cp.async), then loops over
// 64-row tiles: stage A -> sync -> mainloop -> epilogue -> sync.
// CTA tile 64x128, 8 warps: warp w -> rows (w>>2)*32.., cols (w&3)*32..
// bf16 3-term split: Ahi*Bhi + Alo*Bhi + Ahi*Blo.
__global__ __launch_bounds__(256)
void mma_gemm_kernel(const float* __restrict__ A,
                     const __nv_bfloat16* __restrict__ Bhi,
                     const __nv_bfloat16* __restrict__ Blo,
                     const float* __restrict__ bias, float* __restrict__ Cf32,
                     __half* __restrict__ C16,
                     const float* __restrict__ avec,
                     float* __restrict__ asrc, float* __restrict__ adst, int Nrows) {
    extern __shared__ char smem[];
    uint32_t sb = smem_u32(smem);
    int tid = threadIdx.x;
    int l = tid & 31, w = tid >> 5;

    // ---- B copy ONCE: fire-and-forget cp.async (2176 uint4 per matrix) ----
    {
        const uint4* bh4 = (const uint4*)Bhi;
        const uint4* bl4 = (const uint4*)Blo;
#pragma unroll
        for (int it = 0; it < 9; it++) {
            int i = tid + it * 256;
            if (i < 2176) {
                cp_async16(sb + B_HI + i * 16, bh4 + i);
                cp_async16(sb + B_LO + i * 16, bl4 + i);
            }
        }
    }

    int wr = w >> 2, wc = w & 3;           // wr: 0..1 (32-row), wc: 0..3 (32-col)
    int lt = l & 7, lg = l >> 3;

    uint32_t aoff[2];
#pragma unroll
    for (int i = 0; i < 2; i++)
        aoff[i] = (uint32_t)(wr * 32 + i * 16 + lt + (lg & 1) * 8) * 272u + (uint32_t)(lg >> 1) * 16u;
    uint32_t boff[2];
#pragma unroll
    for (int p = 0; p < 2; p++)
        boff[p] = (uint32_t)(wc * 32 + 8 * (2 * p + (lg >> 1)) + lt) * 272u + (uint32_t)(lg & 1) * 16u;

    int num_tiles = (Nrows + 63) >> 6;
    bool first = true;

    for (int tile = blockIdx.x; tile < num_tiles; tile += gridDim.x) {
        int row0 = tile * 64;

        // ---- stage A: 64x128 f32 -> hi/lo bf16 (8 float4 per thread) ----
#pragma unroll
        for (int it = 0; it < 8; it++) {
            int g = tid + it * 256;            // 0..2047
            int r = g >> 5;                    // row 0..63
            int kq = (g & 31) * 4;
            float4 v = make_float4(0.f, 0.f, 0.f, 0.f);
            if (row0 + r < Nrows) v = *(const float4*)(A + (size_t)(row0 + r) * F + kq);
            __nv_bfloat16 h0 = __float2bfloat16(v.x), h1 = __float2bfloat16(v.y);
            __nv_bfloat16 h2 = __float2bfloat16(v.z), h3 = __float2bfloat16(v.w);
            __nv_bfloat16 l0 = __float2bfloat16(v.x - __bfloat162float(h0));
            __nv_bfloat16 l1 = __float2bfloat16(v.y - __bfloat162float(h1));
            __nv_bfloat16 l2 = __float2bfloat16(v.z - __bfloat162float(h2));
            __nv_bfloat16 l3 = __float2bfloat16(v.w - __bfloat162float(h3));
            uint32_t off = (uint32_t)r * 272u + (uint32_t)kq * 2u;
            __nv_bfloat162 hp0 = {h0, h1}, hp1 = {h2, h3};
            __nv_bfloat162 lp0 = {l0, l1}, lp1 = {l2, l3};
            *(uint2*)(smem + A_HI + off) = make_uint2(*(uint32_t*)&hp0, *(uint32_t*)&hp1);
            *(uint2*)(smem + A_LO + off) = make_uint2(*(uint32_t*)&lp0, *(uint32_t*)&lp1);
        }
        if (first) { CP_ASYNC_WAIT_ALL(); first = false; }
        __syncthreads();

        float c[2][4][4];
#pragma unroll
        for (int i = 0; i < 2; i++)
#pragma unroll
            for (int j = 0; j < 4; j++)
#pragma unroll
                for (int q = 0; q < 4; q++) c[i][j][q] = 0.f;

        uint32_t ah[2][4], al[2][4], b[2][4];

#pragma unroll
        for (int ks = 0; ks < 8; ks++) {
            uint32_t k2 = (uint32_t)ks * 32u;
            ldx4(ah[0], sb + A_HI + aoff[0] + k2);
            ldx4(ah[1], sb + A_HI + aoff[1] + k2);
            ldx4(al[0], sb + A_LO + aoff[0] + k2);
            ldx4(al[1], sb + A_LO + aoff[1] + k2);
#pragma unroll
            for (int p = 0; p < 2; p++) ldx4(b[p], sb + B_HI + boff[p] + k2);
#pragma unroll
            for (int i = 0; i < 2; i++)
#pragma unroll
                for (int p = 0; p < 2; p++) {
                    mma_bf16(c[i][2 * p],     ah[i], b[p][0], b[p][1]);
                    mma_bf16(c[i][2 * p + 1], ah[i], b[p][2], b[p][3]);
                    mma_bf16(c[i][2 * p],     al[i], b[p][0], b[p][1]);
                    mma_bf16(c[i][2 * p + 1], al[i], b[p][2], b[p][3]);
                }
#pragma unroll
            for (int p = 0; p < 2; p++) ldx4(b[p], sb + B_LO + boff[p] + k2);
#pragma unroll
            for (int i = 0; i < 2; i++)
#pragma unroll
                for (int p = 0; p < 2; p++) {
                    mma_bf16(c[i][2 * p],     ah[i], b[p][0], b[p][1]);
                    mma_bf16(c[i][2 * p + 1], ah[i], b[p][2], b[p][3]);
                }
        }

        // ---- epilogue ----
#pragma unroll
        for (int i = 0; i < 2; i++) {
#pragma unroll
            for (int rh = 0; rh < 2; rh++) {
                int row = row0 + wr * 32 + i * 16 + rh * 8 + (l >> 2);
                bool valid = (row < Nrows);
                if (valid) {
#pragma unroll
                    for (int j = 0; j < 4; j++) {
                        int col = wc * 32 + 8 * j + 2 * (l & 3);
                        float v0 = c[i][j][2 * rh], v1 = c[i][j][2 * rh + 1];
                        if (bias) { v0 += __ldg(bias + col); v1 += __ldg(bias + col + 1); }
                        if (Cf32) {
                            float2 st; st.x = v0; st.y = v1;
                            *(float2*)(Cf32 + (size_t)row * F + col) = st;
                        }
                        if (C16) {
                            *(__half2*)(C16 + (size_t)row * F + col) =
                                __float22half2_rn(make_float2(v0, v1));
                        }
                    }
                }
                if (avec) {
                    float s[2], d[2];
#pragma unroll
                    for (int q = 0; q < 2; q++) { s[q] = 0.f; d[q] = 0.f; }
#pragma unroll
                    for (int j = 0; j < 4; j++) {
                        int hl = j >> 1;                        // local head 0..1
                        int hh = wc * 2 + hl;                   // global head
                        int f0 = 8 * (j & 1) + 2 * (l & 3);
                        float v0 = c[i][j][2 * rh], v1 = c[i][j][2 * rh + 1];
                        s[hl] += v0 * __ldg(avec + hh * 32 + f0) + v1 * __ldg(avec + hh * 32 + f0 + 1);
                        d[hl] += v0 * __ldg(avec + hh * 32 + 16 + f0) + v1 * __ldg(avec + hh * 32 + 16 + f0 + 1);
                    }
#pragma unroll
                    for (int q = 0; q < 2; q++) {
                        s[q] += __shfl_xor_sync(0xffffffffu, s[q], 1);
                        s[q] += __shfl_xor_sync(0xffffffffu, s[q], 2);
                        d[q] += __shfl_xor_sync(0xffffffffu, d[q], 1);
                        d[q] += __shfl_xor_sync(0xffffffffu, d[q], 2);
                    }
                    if ((l & 3) == 0 && valid) {
#pragma unroll
                        for (int q = 0; q < 2; q++) {
                            asrc[row * H + wc * 2 + q] = s[q];
                            adst[row * H + wc * 2 + q] = d[q];
                        }
                    }
                }
            }
        }
        __syncthreads();   // all warps done reading A smem before next tile overwrites
    }
}

// ---------------- CSR construction ----------------
__global__ void zero_cnt_kernel(int* __restrict__ cnt, int N) {
    int i = blockIdx.x * blockDim.x + threadIdx.x;
    if (i < N) cnt[i] = 0;
}
__global__ void hist_kernel(const int* __restrict__ row, int* __restrict__ cnt, int E) {
    int e = blockIdx.x * blockDim.x + threadIdx.x;
    if (e < E) atomicAdd(cnt + __ldg(row + e), 1);
}

// phase 1: per-block exclusive scan + block totals
__global__ __launch_bounds__(SCAN_B)
void blockscan_kernel(const int* __restrict__ cnt, int* __restrict__ excl,
                      int* __restrict__ bsum, int N) {
    __shared__ int sh[SCAN_B];
    int t = threadIdx.x;
    int i = blockIdx.x * SCAN_B + t;
    int v = (i < N) ? cnt[i] : 0;
    sh[t] = v;
    __syncthreads();
    int run = v;
    for (int off = 1; off < SCAN_B; off <<= 1) {
        int u = (t >= off) ? sh[t - off] : 0;
        __syncthreads();
        run += u;
        sh[t] = run;
        __syncthreads();
    }
    if (i < N) excl[i] = run - v;
    if (t == SCAN_B - 1) bsum[blockIdx.x] = run;
}

// phase 2+3 fused: scan block totals, apply, emit offs + cursor
__global__ __launch_bounds__(SCAN_B)
void scan_apply_kernel(const int* __restrict__ bsum, const int* __restrict__ excl,
                       int* __restrict__ offs, int* __restrict__ cursor,
                       int nb, int N, int E) {
    __shared__ int sh[MAXBLK];
    int t = threadIdx.x;
    int v = (t < nb) ? bsum[t] : 0;
    if (t < MAXBLK) sh[t] = v;
    __syncthreads();
    int run = v;
    for (int off = 1; off < MAXBLK; off <<= 1) {
        int u = (t >= off && t < MAXBLK) ? sh[t - off] : 0;
        __syncthreads();
        if (t < MAXBLK) { run += u; sh[t] = run; }
        __syncthreads();
    }
    if (t < MAXBLK) sh[t] = run - v;     // exclusive block offset
    __syncthreads();
    for (int i = t; i < N; i += SCAN_B) {
        int val = excl[i] + sh[i >> 10];
        offs[i] = val;
        cursor[i] = val;
    }
    if (t == 0) offs[N] = E;
}

__global__ void scatter_kernel(const int* __restrict__ row, const int* __restrict__ col,
                               const float* __restrict__ ev,
                               int* __restrict__ cursor, int2* __restrict__ ecomb, int E) {
    int e = blockIdx.x * blockDim.x + threadIdx.x;
    if (e >= E) return;
    int p = atomicAdd(cursor + __ldg(row + e), 1);
    int2 pk;
    pk.x = __ldg(col + e);
    pk.y = __float_as_int(__ldg(ev + e));
    ecomb[p] = pk;
}

// ---------------- fused edge gather (fp16 h), 2 warps per row ----------------
__global__ __launch_bounds__(256)
void edge_csr_kernel(const int* __restrict__ offs, const int2* __restrict__ ecomb,
                     const float* __restrict__ asrc, const float* __restrict__ adst,
                     const __half* __restrict__ h16,
                     const float* __restrict__ skip, float* __restrict__ out,
                     int N, int mode) {
    __shared__ float red[8][32][5];
    int wib = threadIdx.x >> 5;
    int lane = threadIdx.x & 31;
    int gwid = blockIdx.x * 8 + wib;
    int row = gwid >> 1;
    int half = gwid & 1;
    int head = lane >> 2;
    bool active = (row < N);

    float ax = 0.f, ay = 0.f, az = 0.f, aw = 0.f, wsum = 0.f;
    float asr = 0.f;
    int b0 = 0, e0 = 0;
    if (active) {
        asr = __ldg(asrc + row * H + head);
        int beg = __ldg(offs + row);
        int end = __ldg(offs + row + 1);
        int mid = beg + ((end - beg + 1) >> 1);
        b0 = half ? mid : beg;
        e0 = half ? end : mid;
    }

    int e = b0;
#pragma unroll 1
    for (; e + 3 < e0; e += 4) {
        int2 m[4]; float dd[4]; uint2 hh[4];
#pragma unroll
        for (int q = 0; q < 4; q++) m[q] = __ldg(ecomb + e + q);
#pragma unroll
        for (int q = 0; q < 4; q++) {
            dd[q] = __ldg(adst + m[q].x * H + head);
            hh[q] = *(const uint2*)(h16 + (size_t)m[q].x * F + lane * 4);
        }
#pragma unroll
        for (int q = 0; q < 4; q++) {
            float lg = __int_as_float(m[q].y) * (asr + dd[q]);
            lg = fmaxf(lg, 0.2f * lg);
            float wgt = __expf(lg);
            float2 f0 = __half22float2(*(const __half2*)&hh[q].x);
            float2 f1 = __half22float2(*(const __half2*)&hh[q].y);
            ax += wgt * f0.x; ay += wgt * f0.y;
            az += wgt * f1.x; aw += wgt * f1.y;
            wsum += wgt;
        }
    }
#pragma unroll 1
    for (; e < e0; e++) {
        int2 m = __ldg(ecomb + e);
        float d0 = __ldg(adst + m.x * H + head);
        uint2 hh = *(const uint2*)(h16 + (size_t)m.x * F + lane * 4);
        float l0 = __int_as_float(m.y) * (asr + d0);
        l0 = fmaxf(l0, 0.2f * l0);
        float w0 = __expf(l0);
        float2 f0 = __half22float2(*(const __half2*)&hh.x);
        float2 f1 = __half22float2(*(const __half2*)&hh.y);
        ax += w0 * f0.x; ay += w0 * f0.y; az += w0 * f1.x; aw += w0 * f1.y;
        wsum += w0;
    }

    // odd warps deposit partials
    if (half) {
        red[wib][lane][0] = ax;
        red[wib][lane][1] = ay;
        red[wib][lane][2] = az;
        red[wib][lane][3] = aw;
        red[wib][lane][4] = wsum;
    }
    __syncthreads();

    if (active && !half) {
        ax   += red[wib + 1][lane][0];
        ay   += red[wib + 1][lane][1];
        az   += red[wib + 1][lane][2];
        aw   += red[wib + 1][lane][3];
        wsum += red[wib + 1][lane][4];

        float inv = 1.0f / wsum;
        float4 v;
        v.x = ax * inv; v.y = ay * inv; v.z = az * inv; v.w = aw * inv;
        if (mode == 0) {
            v.x = (v.x > 0.f) ? v.x : expm1f(v.x);
            v.y = (v.y > 0.f) ? v.y : expm1f(v.y);
            v.z = (v.z > 0.f) ? v.z : expm1f(v.z);
            v.w = (v.w > 0.f) ? v.w : expm1f(v.w);
        } else {
            float4 sk = *(const float4*)(skip + (size_t)row * F + lane * 4);
            v.x += sk.x; v.y += sk.y; v.z += sk.z; v.w += sk.w;
        }
        *(float4*)(out + (size_t)row * F + lane * 4) = v;
    }
}

// ---------------- launch ----------------
extern "C" void kernel_launch(void* const* d_in, const int* in_sizes, int n_in,
                              void* d_out, int out_size) {
    const float* x    = (const float*)d_in[0];
    const int*   eidx = (const int*)  d_in[1];
    const float* ev   = (const float*)d_in[2];
    const float* encW = (const float*)d_in[3];
    const float* encb = (const float*)d_in[4];
    const float* Wst  = (const float*)d_in[5];
    const float* ast  = (const float*)d_in[6];
    float* out = (float*)d_out;

    int N = in_sizes[0] / F;
    int E = in_sizes[2];
    const int* row  = eidx;
    const int* colp = eidx + E;

    float *xc, *asrc, *adst;
    __half* h16;
    int *cnt, *excl, *bsum, *offs, *cursor;
    int2* ecomb;
    __nv_bfloat16 *Bhi, *Blo;
    cudaGetSymbolAddress((void**)&xc,     g_xc);
    cudaGetSymbolAddress((void**)&h16,    g_h16);
    cudaGetSymbolAddress((void**)&asrc,   g_asrc);
    cudaGetSymbolAddress((void**)&adst,   g_adst);
    cudaGetSymbolAddress((void**)&cnt,    g_cnt);
    cudaGetSymbolAddress((void**)&excl,   g_excl);
    cudaGetSymbolAddress((void**)&bsum,   g_bsum);
    cudaGetSymbolAddress((void**)&offs,   g_offs);
    cudaGetSymbolAddress((void**)&cursor, g_cursor);
    cudaGetSymbolAddress((void**)&ecomb,  g_ecomb);
    cudaGetSymbolAddress((void**)&Bhi,    g_Bhi);
    cudaGetSymbolAddress((void**)&Blo,    g_Blo);

    static int smem_set = 0;
    if (!smem_set) {
        cudaFuncSetAttribute(mma_gemm_kernel,
                             cudaFuncAttributeMaxDynamicSharedMemorySize, SMEM_TOT);
        smem_set = 1;
    }

    const int TB = 256;
    int num_tiles = (N + 63) / 64;
    int gemm_grid = (num_tiles < GEMM_GRID) ? num_tiles : GEMM_GRID;
    int edge_blocks = (2 * N + 7) / 8;      // 2 warps per row, 8 warps per block
    int scan_blocks = (N + SCAN_B - 1) / SCAN_B;

    // ---- CSR build + weight prep; encoder GEMM at launch index 3 (ncu window) ----
    zero_cnt_kernel<<<(N + TB - 1) / TB, TB>>>(cnt, N);                         // 0
    hist_kernel<<<(E + TB - 1) / TB, TB>>>(row, cnt, E);                        // 1
    prepB_kernel<<<(3 * F * STR + TB - 1) / TB, TB>>>(encW, Wst);               // 2
    // encoder: xc = x @ enc_W + enc_b (f32 out)
    mma_gemm_kernel<<<gemm_grid, 256, SMEM_TOT>>>(x, Bhi, Blo, encb, xc,        // 3
                                                  nullptr, nullptr, nullptr,
                                                  nullptr, N);
    blockscan_kernel<<<scan_blocks, SCAN_B>>>(cnt, excl, bsum, N);              // 4
    scan_apply_kernel<<<1, SCAN_B>>>(bsum, excl, offs, cursor, scan_blocks, N, E); // 5
    scatter_kernel<<<(E + TB - 1) / TB, TB>>>(row, colp, ev, cursor, ecomb, E); // 6

    for (int ell = 0; ell < 2; ell++) {
        const float* al = ast + ell * H * 2 * DH;
        const __nv_bfloat16* bh = Bhi + (1 + ell) * F * STR;
        const __nv_bfloat16* bl = Blo + (1 + ell) * F * STR;

        // h16 = xc @ W (fp16 out), fused asrc/adst
        mma_gemm_kernel<<<gemm_grid, 256, SMEM_TOT>>>(xc, bh, bl, nullptr, nullptr,
                                                      h16, al, asrc, adst, N);

        if (ell == 0) {
            edge_csr_kernel<<<edge_blocks, TB>>>(offs, ecomb, asrc, adst, h16,
                                                 nullptr, xc, N, 0);
        } else {
            edge_csr_kernel<<<edge_blocks, TB>>>(offs, ecomb, asrc, adst, h16,
                                                 xc, out, N, 1);
        }
    }
}

// round 14
// speedup vs baseline: 1.1197x; 1.1197x over previous
#include <cuda_runtime.h>
#include <cuda_bf16.h>
#include <cuda_fp16.h>
#include <cstdint>

#define F     128      // HID == F_IN
#define H     8        // heads
#define DH    16       // dim per head
#define NMAX  65536
#define EMAX  1000000
#define SCAN_B 1024
#define MAXBLK 64      // max scan blocks (ceil(NMAX/1024))

#define STR   136                       // padded fp16 row stride (272 B)
// CTA tile: 64 rows x 128 cols. A hi/lo: 64*272 each; B hi: 128*272.
#define A_HI  0
#define A_LO  (64 * STR * 2)            // 17408
#define B_HI  (2 * 64 * STR * 2)        // 34816
#define SMEM_TOT (B_HI + 128 * STR * 2) // 69632  -> 3 CTAs/SM

#define GEMM_GRID 444                   // 3 CTAs/SM x 148 SMs: one resident wave

// ---------------- device scratch (no allocations allowed) ----------------
__device__ __align__(16) float  g_xc[NMAX * F];
__device__ __align__(16) __half g_h16[NMAX * F];     // fp16 projected features
__device__ __align__(16) float  g_asrc[NMAX * H];
__device__ __align__(16) float  g_adst[NMAX * H];
__device__ int   g_cnt[NMAX];
__device__ int   g_excl[NMAX];
__device__ int   g_bsum[MAXBLK];
__device__ int   g_offs[NMAX + 1];
__device__ int   g_cursor[NMAX];
__device__ __align__(16) int2 g_ecomb[EMAX];         // packed (col, ev-bits)
// prepped weights: B^T [n][k] padded to STR, fp16, 3 matrices
__device__ __align__(16) __half g_Bh[3 * F * STR];

// ---------------- helpers ----------------
__device__ __forceinline__ uint32_t smem_u32(const void* p) {
    uint32_t a;
    asm("{ .reg .u64 t; cvta.to.shared.u64 t, %1; cvt.u32.u64 %0, t; }" : "=r"(a) : "l"(p));
    return a;
}
__device__ __forceinline__ void ldx4(uint32_t* r, uint32_t addr) {
    asm volatile("ldmatrix.sync.aligned.m8n8.x4.shared.b16 {%0,%1,%2,%3}, [%4];"
                 : "=r"(r[0]), "=r"(r[1]), "=r"(r[2]), "=r"(r[3]) : "r"(addr));
}
__device__ __forceinline__ void mma_f16(float* c, const uint32_t* a, uint32_t b0, uint32_t b1) {
    asm volatile("mma.sync.aligned.m16n8k16.row.col.f32.f16.f16.f32 "
                 "{%0,%1,%2,%3}, {%4,%5,%6,%7}, {%8,%9}, {%0,%1,%2,%3};"
                 : "+f"(c[0]), "+f"(c[1]), "+f"(c[2]), "+f"(c[3])
                 : "r"(a[0]), "r"(a[1]), "r"(a[2]), "r"(a[3]), "r"(b0), "r"(b1));
}
__device__ __forceinline__ void cp_async16(uint32_t saddr, const void* gptr) {
    asm volatile("cp.async.cg.shared.global [%0], [%1], 16;" :: "r"(saddr), "l"(gptr) : "memory");
}
#define CP_ASYNC_WAIT_ALL() asm volatile("cp.async.wait_all;" ::: "memory")

// ---------------- weight prep: W[k][n] -> B^T[n][k] padded, fp16 ----------------
__global__ void prepB_kernel(const float* __restrict__ encW,
                             const float* __restrict__ Wst) {
    int idx = blockIdx.x * blockDim.x + threadIdx.x;
    if (idx >= 3 * F * STR) return;
    int mat = idx / (F * STR);
    int t = idx % (F * STR);
    int n = t / STR, k = t % STR;
    float w = 0.f;
    if (k < F) {
        if (mat == 0) w = encW[k * F + n];
        else {
            int hh = n >> 4, f = n & 15;
            w = Wst[(mat - 1) * (H * F * DH) + (hh * F + k) * DH + f];
        }
    }
    g_Bh[idx] = __float2half_rn(w);
}

// ---------------- persistent HMMA GEMM: C = A @ W (+bias), fused alpha ----------------
// fp16 exact-A split: (Ahi + Alo) @ Bh.  A split is exact; only B is rounded.
// grid = GEMM_GRID; each CTA stages B ONCE (cp.async), loops over 64-row tiles.
// CTA tile 64x128, 8 warps: warp w -> rows (w>>2)*32.., cols (w&3)*32..
__global__ __launch_bounds__(256)
void mma_gemm_kernel(const float* __restrict__ A,
                     const __half* __restrict__ Bh,
                     const float* __restrict__ bias, float* __restrict__ Cf32,
                     __half* __restrict__ C16,
                     const float* __restrict__ avec,
                     float* __restrict__ asrc, float* __restrict__ adst, int Nrows) {
    extern __shared__ char smem[];
    uint32_t sb = smem_u32(smem);
    int tid = threadIdx.x;
    int l = tid & 31, w = tid >> 5;

    // ---- B copy ONCE: fire-and-forget cp.async (2176 uint4) ----
    {
        const uint4* bh4 = (const uint4*)Bh;
#pragma unroll
        for (int it = 0; it < 9; it++) {
            int i = tid + it * 256;
            if (i < 2176) cp_async16(sb + B_HI + i * 16, bh4 + i);
        }
    }

    int wr = w >> 2, wc = w & 3;           // wr: 0..1 (32-row), wc: 0..3 (32-col)
    int lt = l & 7, lg = l >> 3;

    uint32_t aoff[2];
#pragma unroll
    for (int i = 0; i < 2; i++)
        aoff[i] = (uint32_t)(wr * 32 + i * 16 + lt + (lg & 1) * 8) * 272u + (uint32_t)(lg >> 1) * 16u;
    uint32_t boff[2];
#pragma unroll
    for (int p = 0; p < 2; p++)
        boff[p] = (uint32_t)(wc * 32 + 8 * (2 * p + (lg >> 1)) + lt) * 272u + (uint32_t)(lg & 1) * 16u;

    int num_tiles = (Nrows + 63) >> 6;
    bool first = true;

    for (int tile = blockIdx.x; tile < num_tiles; tile += gridDim.x) {
        int row0 = tile * 64;

        // ---- stage A: 64x128 f32 -> fp16 hi/lo (exact split), 8 float4/thread ----
#pragma unroll
        for (int it = 0; it < 8; it++) {
            int g = tid + it * 256;            // 0..2047
            int r = g >> 5;                    // row 0..63
            int kq = (g & 31) * 4;
            float4 v = make_float4(0.f, 0.f, 0.f, 0.f);
            if (row0 + r < Nrows) v = *(const float4*)(A + (size_t)(row0 + r) * F + kq);
            __half h0 = __float2half_rn(v.x), h1 = __float2half_rn(v.y);
            __half h2 = __float2half_rn(v.z), h3 = __float2half_rn(v.w);
            __half l0 = __float2half_rn(v.x - __half2float(h0));
            __half l1 = __float2half_rn(v.y - __half2float(h1));
            __half l2 = __float2half_rn(v.z - __half2float(h2));
            __half l3 = __float2half_rn(v.w - __half2float(h3));
            uint32_t off = (uint32_t)r * 272u + (uint32_t)kq * 2u;
            __half2 hp0 = {h0, h1}, hp1 = {h2, h3};
            __half2 lp0 = {l0, l1}, lp1 = {l2, l3};
            *(uint2*)(smem + A_HI + off) = make_uint2(*(uint32_t*)&hp0, *(uint32_t*)&hp1);
            *(uint2*)(smem + A_LO + off) = make_uint2(*(uint32_t*)&lp0, *(uint32_t*)&lp1);
        }
        if (first) { CP_ASYNC_WAIT_ALL(); first = false; }
        __syncthreads();

        float c[2][4][4];
#pragma unroll
        for (int i = 0; i < 2; i++)
#pragma unroll
            for (int j = 0; j < 4; j++)
#pragma unroll
                for (int q = 0; q < 4; q++) c[i][j][q] = 0.f;

        uint32_t ah[2][4], al[2][4], b[2][4];

#pragma unroll
        for (int ks = 0; ks < 8; ks++) {
            uint32_t k2 = (uint32_t)ks * 32u;
            ldx4(ah[0], sb + A_HI + aoff[0] + k2);
            ldx4(ah[1], sb + A_HI + aoff[1] + k2);
            ldx4(al[0], sb + A_LO + aoff[0] + k2);
            ldx4(al[1], sb + A_LO + aoff[1] + k2);
#pragma unroll
            for (int p = 0; p < 2; p++) ldx4(b[p], sb + B_HI + boff[p] + k2);
#pragma unroll
            for (int i = 0; i < 2; i++)
#pragma unroll
                for (int p = 0; p < 2; p++) {
                    mma_f16(c[i][2 * p],     ah[i], b[p][0], b[p][1]);
                    mma_f16(c[i][2 * p + 1], ah[i], b[p][2], b[p][3]);
                    mma_f16(c[i][2 * p],     al[i], b[p][0], b[p][1]);
                    mma_f16(c[i][2 * p + 1], al[i], b[p][2], b[p][3]);
                }
        }

        // ---- epilogue ----
#pragma unroll
        for (int i = 0; i < 2; i++) {
#pragma unroll
            for (int rh = 0; rh < 2; rh++) {
                int row = row0 + wr * 32 + i * 16 + rh * 8 + (l >> 2);
                bool valid = (row < Nrows);
                if (valid) {
#pragma unroll
                    for (int j = 0; j < 4; j++) {
                        int col = wc * 32 + 8 * j + 2 * (l & 3);
                        float v0 = c[i][j][2 * rh], v1 = c[i][j][2 * rh + 1];
                        if (bias) { v0 += __ldg(bias + col); v1 += __ldg(bias + col + 1); }
                        if (Cf32) {
                            float2 st; st.x = v0; st.y = v1;
                            *(float2*)(Cf32 + (size_t)row * F + col) = st;
                        }
                        if (C16) {
                            *(__half2*)(C16 + (size_t)row * F + col) =
                                __float22half2_rn(make_float2(v0, v1));
                        }
                    }
                }
                if (avec) {
                    float s[2], d[2];
#pragma unroll
                    for (int q = 0; q < 2; q++) { s[q] = 0.f; d[q] = 0.f; }
#pragma unroll
                    for (int j = 0; j < 4; j++) {
                        int hl = j >> 1;                        // local head 0..1
                        int hh = wc * 2 + hl;                   // global head
                        int f0 = 8 * (j & 1) + 2 * (l & 3);
                        float v0 = c[i][j][2 * rh], v1 = c[i][j][2 * rh + 1];
                        s[hl] += v0 * __ldg(avec + hh * 32 + f0) + v1 * __ldg(avec + hh * 32 + f0 + 1);
                        d[hl] += v0 * __ldg(avec + hh * 32 + 16 + f0) + v1 * __ldg(avec + hh * 32 + 16 + f0 + 1);
                    }
#pragma unroll
                    for (int q = 0; q < 2; q++) {
                        s[q] += __shfl_xor_sync(0xffffffffu, s[q], 1);
                        s[q] += __shfl_xor_sync(0xffffffffu, s[q], 2);
                        d[q] += __shfl_xor_sync(0xffffffffu, d[q], 1);
                        d[q] += __shfl_xor_sync(0xffffffffu, d[q], 2);
                    }
                    if ((l & 3) == 0 && valid) {
#pragma unroll
                        for (int q = 0; q < 2; q++) {
                            asrc[row * H + wc * 2 + q] = s[q];
                            adst[row * H + wc * 2 + q] = d[q];
                        }
                    }
                }
            }
        }
        __syncthreads();   // all warps done reading A smem before next tile overwrites
    }
}

// ---------------- CSR construction ----------------
__global__ void zero_cnt_kernel(int* __restrict__ cnt, int N) {
    int i = blockIdx.x * blockDim.x + threadIdx.x;
    if (i < N) cnt[i] = 0;
}
__global__ void hist_kernel(const int* __restrict__ row, int* __restrict__ cnt, int E) {
    int e = blockIdx.x * blockDim.x + threadIdx.x;
    if (e < E) atomicAdd(cnt + __ldg(row + e), 1);
}

// phase 1: per-block exclusive scan + block totals
__global__ __launch_bounds__(SCAN_B)
void blockscan_kernel(const int* __restrict__ cnt, int* __restrict__ excl,
                      int* __restrict__ bsum, int N) {
    __shared__ int sh[SCAN_B];
    int t = threadIdx.x;
    int i = blockIdx.x * SCAN_B + t;
    int v = (i < N) ? cnt[i] : 0;
    sh[t] = v;
    __syncthreads();
    int run = v;
    for (int off = 1; off < SCAN_B; off <<= 1) {
        int u = (t >= off) ? sh[t - off] : 0;
        __syncthreads();
        run += u;
        sh[t] = run;
        __syncthreads();
    }
    if (i < N) excl[i] = run - v;
    if (t == SCAN_B - 1) bsum[blockIdx.x] = run;
}

// phase 2+3 fused: scan block totals, apply, emit offs + cursor
__global__ __launch_bounds__(SCAN_B)
void scan_apply_kernel(const int* __restrict__ bsum, const int* __restrict__ excl,
                       int* __restrict__ offs, int* __restrict__ cursor,
                       int nb, int N, int E) {
    __shared__ int sh[MAXBLK];
    int t = threadIdx.x;
    int v = (t < nb) ? bsum[t] : 0;
    if (t < MAXBLK) sh[t] = v;
    __syncthreads();
    int run = v;
    for (int off = 1; off < MAXBLK; off <<= 1) {
        int u = (t >= off && t < MAXBLK) ? sh[t - off] : 0;
        __syncthreads();
        if (t < MAXBLK) { run += u; sh[t] = run; }
        __syncthreads();
    }
    if (t < MAXBLK) sh[t] = run - v;     // exclusive block offset
    __syncthreads();
    for (int i = t; i < N; i += SCAN_B) {
        int val = excl[i] + sh[i >> 10];
        offs[i] = val;
        cursor[i] = val;
    }
    if (t == 0) offs[N] = E;
}

__global__ void scatter_kernel(const int* __restrict__ row, const int* __restrict__ col,
                               const float* __restrict__ ev,
                               int* __restrict__ cursor, int2* __restrict__ ecomb, int E) {
    int e = blockIdx.x * blockDim.x + threadIdx.x;
    if (e >= E) return;
    int p = atomicAdd(cursor + __ldg(row + e), 1);
    int2 pk;
    pk.x = __ldg(col + e);
    pk.y = __float_as_int(__ldg(ev + e));
    ecomb[p] = pk;
}

// ---------------- fused edge gather (fp16 h), one warp per row (R8 proven) ----------------
__global__ __launch_bounds__(256)
void edge_csr_kernel(const int* __restrict__ offs, const int2* __restrict__ ecomb,
                     const float* __restrict__ asrc, const float* __restrict__ adst,
                     const __half* __restrict__ h16,
                     const float* __restrict__ skip, float* __restrict__ out,
                     int N, int mode) {
    int gwid = (blockIdx.x * blockDim.x + threadIdx.x) >> 5;
    if (gwid >= N) return;
    int lane = threadIdx.x & 31;
    int head = lane >> 2;

    float asr = __ldg(asrc + gwid * H + head);
    int beg = __ldg(offs + gwid);
    int end = __ldg(offs + gwid + 1);

    float ax = 0.f, ay = 0.f, az = 0.f, aw = 0.f, wsum = 0.f;

    int e = beg;
#pragma unroll 1
    for (; e + 3 < end; e += 4) {
        int2 m[4]; float dd[4]; uint2 hh[4];
#pragma unroll
        for (int q = 0; q < 4; q++) m[q] = __ldg(ecomb + e + q);
#pragma unroll
        for (int q = 0; q < 4; q++) {
            dd[q] = __ldg(adst + m[q].x * H + head);
            hh[q] = *(const uint2*)(h16 + (size_t)m[q].x * F + lane * 4);
        }
#pragma unroll
        for (int q = 0; q < 4; q++) {
            float lg = __int_as_float(m[q].y) * (asr + dd[q]);
            lg = fmaxf(lg, 0.2f * lg);
            float wgt = __expf(lg);
            float2 f0 = __half22float2(*(const __half2*)&hh[q].x);
            float2 f1 = __half22float2(*(const __half2*)&hh[q].y);
            ax += wgt * f0.x; ay += wgt * f0.y;
            az += wgt * f1.x; aw += wgt * f1.y;
            wsum += wgt;
        }
    }
#pragma unroll 1
    for (; e < end; e++) {
        int2 m = __ldg(ecomb + e);
        float d0 = __ldg(adst + m.x * H + head);
        uint2 hh = *(const uint2*)(h16 + (size_t)m.x * F + lane * 4);
        float l0 = __int_as_float(m.y) * (asr + d0);
        l0 = fmaxf(l0, 0.2f * l0);
        float w0 = __expf(l0);
        float2 f0 = __half22float2(*(const __half2*)&hh.x);
        float2 f1 = __half22float2(*(const __half2*)&hh.y);
        ax += w0 * f0.x; ay += w0 * f0.y; az += w0 * f1.x; aw += w0 * f1.y;
        wsum += w0;
    }

    float inv = 1.0f / wsum;
    float4 v;
    v.x = ax * inv; v.y = ay * inv; v.z = az * inv; v.w = aw * inv;
    if (mode == 0) {
        v.x = (v.x > 0.f) ? v.x : expm1f(v.x);
        v.y = (v.y > 0.f) ? v.y : expm1f(v.y);
        v.z = (v.z > 0.f) ? v.z : expm1f(v.z);
        v.w = (v.w > 0.f) ? v.w : expm1f(v.w);
    } else {
        float4 sk = *(const float4*)(skip + (size_t)gwid * F + lane * 4);
        v.x += sk.x; v.y += sk.y; v.z += sk.z; v.w += sk.w;
    }
    *(float4*)(out + (size_t)gwid * F + lane * 4) = v;
}

// ---------------- launch ----------------
extern "C" void kernel_launch(void* const* d_in, const int* in_sizes, int n_in,
                              void* d_out, int out_size) {
    const float* x    = (const float*)d_in[0];
    const int*   eidx = (const int*)  d_in[1];
    const float* ev   = (const float*)d_in[2];
    const float* encW = (const float*)d_in[3];
    const float* encb = (const float*)d_in[4];
    const float* Wst  = (const float*)d_in[5];
    const float* ast  = (const float*)d_in[6];
    float* out = (float*)d_out;

    int N = in_sizes[0] / F;
    int E = in_sizes[2];
    const int* row  = eidx;
    const int* colp = eidx + E;

    float *xc, *asrc, *adst;
    __half *h16, *Bh;
    int *cnt, *excl, *bsum, *offs, *cursor;
    int2* ecomb;
    cudaGetSymbolAddress((void**)&xc,     g_xc);
    cudaGetSymbolAddress((void**)&h16,    g_h16);
    cudaGetSymbolAddress((void**)&asrc,   g_asrc);
    cudaGetSymbolAddress((void**)&adst,   g_adst);
    cudaGetSymbolAddress((void**)&cnt,    g_cnt);
    cudaGetSymbolAddress((void**)&excl,   g_excl);
    cudaGetSymbolAddress((void**)&bsum,   g_bsum);
    cudaGetSymbolAddress((void**)&offs,   g_offs);
    cudaGetSymbolAddress((void**)&cursor, g_cursor);
    cudaGetSymbolAddress((void**)&ecomb,  g_ecomb);
    cudaGetSymbolAddress((void**)&Bh,     g_Bh);

    static int smem_set = 0;
    if (!smem_set) {
        cudaFuncSetAttribute(mma_gemm_kernel,
                             cudaFuncAttributeMaxDynamicSharedMemorySize, SMEM_TOT);
        smem_set = 1;
    }

    const int TB = 256;
    int num_tiles = (N + 63) / 64;
    int gemm_grid = (num_tiles < GEMM_GRID) ? num_tiles : GEMM_GRID;
    int edge_blocks = (N * 32 + TB - 1) / TB;
    int scan_blocks = (N + SCAN_B - 1) / SCAN_B;

    // ---- CSR build + weight prep; encoder GEMM at launch index 3 (ncu window) ----
    zero_cnt_kernel<<<(N + TB - 1) / TB, TB>>>(cnt, N);                         // 0
    hist_kernel<<<(E + TB - 1) / TB, TB>>>(row, cnt, E);                        // 1
    prepB_kernel<<<(3 * F * STR + TB - 1) / TB, TB>>>(encW, Wst);               // 2
    // encoder: xc = x @ enc_W + enc_b (f32 out)
    mma_gemm_kernel<<<gemm_grid, 256, SMEM_TOT>>>(x, Bh, encb, xc,              // 3
                                                  nullptr, nullptr, nullptr,
                                                  nullptr, N);
    blockscan_kernel<<<scan_blocks, SCAN_B>>>(cnt, excl, bsum, N);              // 4
    scan_apply_kernel<<<1, SCAN_B>>>(bsum, excl, offs, cursor, scan_blocks, N, E); // 5
    scatter_kernel<<<(E + TB - 1) / TB, TB>>>(row, colp, ev, cursor, ecomb, E); // 6

    for (int ell = 0; ell < 2; ell++) {
        const float* al = ast + ell * H * 2 * DH;
        const __half* bh = Bh + (1 + ell) * F * STR;

        // h16 = xc @ W (fp16 out), fused asrc/adst
        mma_gemm_kernel<<<gemm_grid, 256, SMEM_TOT>>>(xc, bh, nullptr, nullptr,
                                                      h16, al, asrc, adst, N);

        if (ell == 0) {
            edge_csr_kernel<<<edge_blocks, TB>>>(offs, ecomb, asrc, adst, h16,
                                                 nullptr, xc, N, 0);
        } else {
            edge_csr_kernel<<<edge_blocks, TB>>>(offs, ecomb, asrc, adst, h16,
                                                 xc, out, N, 1);
        }
    }
}

// round 15
// speedup vs baseline: 1.2045x; 1.0757x over previous
#include <cuda_runtime.h>
#include <cuda_bf16.h>
#include <cuda_fp16.h>
#include <cstdint>

#define F     128      // HID == F_IN
#define H     8        // heads
#define DH    16       // dim per head
#define NMAX  65536
#define EMAX  1000000
#define SCAN_B 1024
#define MAXBLK 64      // max scan blocks (ceil(NMAX/1024))

#define STR   136                       // padded fp16 row stride (272 B)
// CTA tile: 64 rows x 128 cols. A hi/lo: 64*272 each; B hi: 128*272.
#define A_HI  0
#define A_LO  (64 * STR * 2)            // 17408
#define B_HI  (2 * 64 * STR * 2)        // 34816
#define SMEM_TOT (B_HI + 128 * STR * 2) // 69632  -> 3 CTAs/SM

#define GEMM_GRID 444                   // 3 CTAs/SM x 148 SMs: one resident wave

// ---------------- device scratch (no allocations allowed) ----------------
__device__ __align__(16) float  g_xc[NMAX * F];
__device__ __align__(16) __half g_h16[NMAX * F];     // fp16 projected features
__device__ __align__(16) float  g_asrc[NMAX * H];
__device__ __align__(16) float  g_adst[NMAX * H];
__device__ int   g_cnt[NMAX];
__device__ int   g_excl[NMAX];
__device__ int   g_bsum[MAXBLK];
__device__ int   g_offs[NMAX + 1];
__device__ int   g_cursor[NMAX];
__device__ __align__(16) int2 g_ecomb[EMAX];         // packed (col, ev-bits)
// prepped weights: B^T [n][k] padded to STR, fp16, 3 matrices
__device__ __align__(16) __half g_Bh[3 * F * STR];

// ---------------- helpers ----------------
__device__ __forceinline__ uint32_t smem_u32(const void* p) {
    uint32_t a;
    asm("{ .reg .u64 t; cvta.to.shared.u64 t, %1; cvt.u32.u64 %0, t; }" : "=r"(a) : "l"(p));
    return a;
}
__device__ __forceinline__ void ldx4(uint32_t* r, uint32_t addr) {
    asm volatile("ldmatrix.sync.aligned.m8n8.x4.shared.b16 {%0,%1,%2,%3}, [%4];"
                 : "=r"(r[0]), "=r"(r[1]), "=r"(r[2]), "=r"(r[3]) : "r"(addr));
}
__device__ __forceinline__ void mma_f16(float* c, const uint32_t* a, uint32_t b0, uint32_t b1) {
    asm volatile("mma.sync.aligned.m16n8k16.row.col.f32.f16.f16.f32 "
                 "{%0,%1,%2,%3}, {%4,%5,%6,%7}, {%8,%9}, {%0,%1,%2,%3};"
                 : "+f"(c[0]), "+f"(c[1]), "+f"(c[2]), "+f"(c[3])
                 : "r"(a[0]), "r"(a[1]), "r"(a[2]), "r"(a[3]), "r"(b0), "r"(b1));
}
__device__ __forceinline__ void cp_async16(uint32_t saddr, const void* gptr) {
    asm volatile("cp.async.cg.shared.global [%0], [%1], 16;" :: "r"(saddr), "l"(gptr) : "memory");
}
#define CP_ASYNC_WAIT_ALL() asm volatile("cp.async.wait_all;" ::: "memory")

// ---------------- weight prep: W[k][n] -> B^T[n][k] padded, fp16 ----------------
__global__ void prepB_kernel(const float* __restrict__ encW,
                             const float* __restrict__ Wst) {
    int idx = blockIdx.x * blockDim.x + threadIdx.x;
    if (idx >= 3 * F * STR) return;
    int mat = idx / (F * STR);
    int t = idx % (F * STR);
    int n = t / STR, k = t % STR;
    float w = 0.f;
    if (k < F) {
        if (mat == 0) w = encW[k * F + n];
        else {
            int hh = n >> 4, f = n & 15;
            w = Wst[(mat - 1) * (H * F * DH) + (hh * F + k) * DH + f];
        }
    }
    g_Bh[idx] = __float2half_rn(w);
}

// ---------------- persistent HMMA GEMM: C = A @ W (+bias), fused alpha ----------------
// fp16 exact-A split: (Ahi + Alo) @ Bh.  A split is exact; only B is rounded.
__global__ __launch_bounds__(256)
void mma_gemm_kernel(const float* __restrict__ A,
                     const __half* __restrict__ Bh,
                     const float* __restrict__ bias, float* __restrict__ Cf32,
                     __half* __restrict__ C16,
                     const float* __restrict__ avec,
                     float* __restrict__ asrc, float* __restrict__ adst, int Nrows) {
    extern __shared__ char smem[];
    uint32_t sb = smem_u32(smem);
    int tid = threadIdx.x;
    int l = tid & 31, w = tid >> 5;

    // ---- B copy ONCE: fire-and-forget cp.async (2176 uint4) ----
    {
        const uint4* bh4 = (const uint4*)Bh;
#pragma unroll
        for (int it = 0; it < 9; it++) {
            int i = tid + it * 256;
            if (i < 2176) cp_async16(sb + B_HI + i * 16, bh4 + i);
        }
    }

    int wr = w >> 2, wc = w & 3;           // wr: 0..1 (32-row), wc: 0..3 (32-col)
    int lt = l & 7, lg = l >> 3;

    uint32_t aoff[2];
#pragma unroll
    for (int i = 0; i < 2; i++)
        aoff[i] = (uint32_t)(wr * 32 + i * 16 + lt + (lg & 1) * 8) * 272u + (uint32_t)(lg >> 1) * 16u;
    uint32_t boff[2];
#pragma unroll
    for (int p = 0; p < 2; p++)
        boff[p] = (uint32_t)(wc * 32 + 8 * (2 * p + (lg >> 1)) + lt) * 272u + (uint32_t)(lg & 1) * 16u;

    int num_tiles = (Nrows + 63) >> 6;
    bool first = true;

    for (int tile = blockIdx.x; tile < num_tiles; tile += gridDim.x) {
        int row0 = tile * 64;

        // ---- stage A: 64x128 f32 -> fp16 hi/lo (exact split), 8 float4/thread ----
#pragma unroll
        for (int it = 0; it < 8; it++) {
            int g = tid + it * 256;            // 0..2047
            int r = g >> 5;                    // row 0..63
            int kq = (g & 31) * 4;
            float4 v = make_float4(0.f, 0.f, 0.f, 0.f);
            if (row0 + r < Nrows) v = *(const float4*)(A + (size_t)(row0 + r) * F + kq);
            __half h0 = __float2half_rn(v.x), h1 = __float2half_rn(v.y);
            __half h2 = __float2half_rn(v.z), h3 = __float2half_rn(v.w);
            __half l0 = __float2half_rn(v.x - __half2float(h0));
            __half l1 = __float2half_rn(v.y - __half2float(h1));
            __half l2 = __float2half_rn(v.z - __half2float(h2));
            __half l3 = __float2half_rn(v.w - __half2float(h3));
            uint32_t off = (uint32_t)r * 272u + (uint32_t)kq * 2u;
            __half2 hp0 = {h0, h1}, hp1 = {h2, h3};
            __half2 lp0 = {l0, l1}, lp1 = {l2, l3};
            *(uint2*)(smem + A_HI + off) = make_uint2(*(uint32_t*)&hp0, *(uint32_t*)&hp1);
            *(uint2*)(smem + A_LO + off) = make_uint2(*(uint32_t*)&lp0, *(uint32_t*)&lp1);
        }
        if (first) { CP_ASYNC_WAIT_ALL(); first = false; }
        __syncthreads();

        float c[2][4][4];
#pragma unroll
        for (int i = 0; i < 2; i++)
#pragma unroll
            for (int j = 0; j < 4; j++)
#pragma unroll
                for (int q = 0; q < 4; q++) c[i][j][q] = 0.f;

        uint32_t ah[2][4], al[2][4], b[2][4];

#pragma unroll
        for (int ks = 0; ks < 8; ks++) {
            uint32_t k2 = (uint32_t)ks * 32u;
            ldx4(ah[0], sb + A_HI + aoff[0] + k2);
            ldx4(ah[1], sb + A_HI + aoff[1] + k2);
            ldx4(al[0], sb + A_LO + aoff[0] + k2);
            ldx4(al[1], sb + A_LO + aoff[1] + k2);
#pragma unroll
            for (int p = 0; p < 2; p++) ldx4(b[p], sb + B_HI + boff[p] + k2);
#pragma unroll
            for (int i = 0; i < 2; i++)
#pragma unroll
                for (int p = 0; p < 2; p++) {
                    mma_f16(c[i][2 * p],     ah[i], b[p][0], b[p][1]);
                    mma_f16(c[i][2 * p + 1], ah[i], b[p][2], b[p][3]);
                    mma_f16(c[i][2 * p],     al[i], b[p][0], b[p][1]);
                    mma_f16(c[i][2 * p + 1], al[i], b[p][2], b[p][3]);
                }
        }

        // ---- epilogue ----
#pragma unroll
        for (int i = 0; i < 2; i++) {
#pragma unroll
            for (int rh = 0; rh < 2; rh++) {
                int row = row0 + wr * 32 + i * 16 + rh * 8 + (l >> 2);
                bool valid = (row < Nrows);
                if (valid) {
#pragma unroll
                    for (int j = 0; j < 4; j++) {
                        int col = wc * 32 + 8 * j + 2 * (l & 3);
                        float v0 = c[i][j][2 * rh], v1 = c[i][j][2 * rh + 1];
                        if (bias) { v0 += __ldg(bias + col); v1 += __ldg(bias + col + 1); }
                        if (Cf32) {
                            float2 st; st.x = v0; st.y = v1;
                            *(float2*)(Cf32 + (size_t)row * F + col) = st;
                        }
                        if (C16) {
                            *(__half2*)(C16 + (size_t)row * F + col) =
                                __float22half2_rn(make_float2(v0, v1));
                        }
                    }
                }
                if (avec) {
                    float s[2], d[2];
#pragma unroll
                    for (int q = 0; q < 2; q++) { s[q] = 0.f; d[q] = 0.f; }
#pragma unroll
                    for (int j = 0; j < 4; j++) {
                        int hl = j >> 1;                        // local head 0..1
                        int hh = wc * 2 + hl;                   // global head
                        int f0 = 8 * (j & 1) + 2 * (l & 3);
                        float v0 = c[i][j][2 * rh], v1 = c[i][j][2 * rh + 1];
                        s[hl] += v0 * __ldg(avec + hh * 32 + f0) + v1 * __ldg(avec + hh * 32 + f0 + 1);
                        d[hl] += v0 * __ldg(avec + hh * 32 + 16 + f0) + v1 * __ldg(avec + hh * 32 + 16 + f0 + 1);
                    }
#pragma unroll
                    for (int q = 0; q < 2; q++) {
                        s[q] += __shfl_xor_sync(0xffffffffu, s[q], 1);
                        s[q] += __shfl_xor_sync(0xffffffffu, s[q], 2);
                        d[q] += __shfl_xor_sync(0xffffffffu, d[q], 1);
                        d[q] += __shfl_xor_sync(0xffffffffu, d[q], 2);
                    }
                    if ((l & 3) == 0 && valid) {
#pragma unroll
                        for (int q = 0; q < 2; q++) {
                            asrc[row * H + wc * 2 + q] = s[q];
                            adst[row * H + wc * 2 + q] = d[q];
                        }
                    }
                }
            }
        }
        __syncthreads();   // all warps done reading A smem before next tile overwrites
    }
}

// ---------------- CSR construction ----------------
__global__ void zero_cnt_kernel(int* __restrict__ cnt, int N) {
    int i = blockIdx.x * blockDim.x + threadIdx.x;
    if (i < N) cnt[i] = 0;
}
__global__ void hist_kernel(const int* __restrict__ row, int* __restrict__ cnt, int E) {
    int e = blockIdx.x * blockDim.x + threadIdx.x;
    if (e < E) atomicAdd(cnt + __ldg(row + e), 1);
}

// phase 1: per-block exclusive scan + block totals
__global__ __launch_bounds__(SCAN_B)
void blockscan_kernel(const int* __restrict__ cnt, int* __restrict__ excl,
                      int* __restrict__ bsum, int N) {
    __shared__ int sh[SCAN_B];
    int t = threadIdx.x;
    int i = blockIdx.x * SCAN_B + t;
    int v = (i < N) ? cnt[i] : 0;
    sh[t] = v;
    __syncthreads();
    int run = v;
    for (int off = 1; off < SCAN_B; off <<= 1) {
        int u = (t >= off) ? sh[t - off] : 0;
        __syncthreads();
        run += u;
        sh[t] = run;
        __syncthreads();
    }
    if (i < N) excl[i] = run - v;
    if (t == SCAN_B - 1) bsum[blockIdx.x] = run;
}

// phase 2+3 fused: scan block totals, apply, emit offs + cursor
__global__ __launch_bounds__(SCAN_B)
void scan_apply_kernel(const int* __restrict__ bsum, const int* __restrict__ excl,
                       int* __restrict__ offs, int* __restrict__ cursor,
                       int nb, int N, int E) {
    __shared__ int sh[MAXBLK];
    int t = threadIdx.x;
    int v = (t < nb) ? bsum[t] : 0;
    if (t < MAXBLK) sh[t] = v;
    __syncthreads();
    int run = v;
    for (int off = 1; off < MAXBLK; off <<= 1) {
        int u = (t >= off && t < MAXBLK) ? sh[t - off] : 0;
        __syncthreads();
        if (t < MAXBLK) { run += u; sh[t] = run; }
        __syncthreads();
    }
    if (t < MAXBLK) sh[t] = run - v;     // exclusive block offset
    __syncthreads();
    for (int i = t; i < N; i += SCAN_B) {
        int val = excl[i] + sh[i >> 10];
        offs[i] = val;
        cursor[i] = val;
    }
    if (t == 0) offs[N] = E;
}

__global__ void scatter_kernel(const int* __restrict__ row, const int* __restrict__ col,
                               const float* __restrict__ ev,
                               int* __restrict__ cursor, int2* __restrict__ ecomb, int E) {
    int e = blockIdx.x * blockDim.x + threadIdx.x;
    if (e >= E) return;
    int p = atomicAdd(cursor + __ldg(row + e), 1);
    int2 pk;
    pk.x = __ldg(col + e);
    pk.y = __float_as_int(__ldg(ev + e));
    ecomb[p] = pk;
}

// ---------------- fused edge gather (fp16 h), one warp per row ----------------
__global__ __launch_bounds__(256)
void edge_csr_kernel(const int* __restrict__ offs, const int2* __restrict__ ecomb,
                     const float* __restrict__ asrc, const float* __restrict__ adst,
                     const __half* __restrict__ h16,
                     const float* __restrict__ skip, float* __restrict__ out,
                     int N, int mode) {
    int gwid = (blockIdx.x * blockDim.x + threadIdx.x) >> 5;
    if (gwid >= N) return;
    int lane = threadIdx.x & 31;
    int head = lane >> 2;

    float asr = __ldg(asrc + gwid * H + head);
    int beg = __ldg(offs + gwid);
    int end = __ldg(offs + gwid + 1);

    float ax = 0.f, ay = 0.f, az = 0.f, aw = 0.f, wsum = 0.f;

    int e = beg;
#pragma unroll 1
    for (; e + 3 < end; e += 4) {
        int2 m[4]; float dd[4]; uint2 hh[4];
#pragma unroll
        for (int q = 0; q < 4; q++) m[q] = __ldg(ecomb + e + q);
#pragma unroll
        for (int q = 0; q < 4; q++) {
            dd[q] = __ldg(adst + m[q].x * H + head);
            hh[q] = *(const uint2*)(h16 + (size_t)m[q].x * F + lane * 4);
        }
#pragma unroll
        for (int q = 0; q < 4; q++) {
            float lg = __int_as_float(m[q].y) * (asr + dd[q]);
            lg = fmaxf(lg, 0.2f * lg);
            float wgt = __expf(lg);
            float2 f0 = __half22float2(*(const __half2*)&hh[q].x);
            float2 f1 = __half22float2(*(const __half2*)&hh[q].y);
            ax += wgt * f0.x; ay += wgt * f0.y;
            az += wgt * f1.x; aw += wgt * f1.y;
            wsum += wgt;
        }
    }
#pragma unroll 1
    for (; e < end; e++) {
        int2 m = __ldg(ecomb + e);
        float d0 = __ldg(adst + m.x * H + head);
        uint2 hh = *(const uint2*)(h16 + (size_t)m.x * F + lane * 4);
        float l0 = __int_as_float(m.y) * (asr + d0);
        l0 = fmaxf(l0, 0.2f * l0);
        float w0 = __expf(l0);
        float2 f0 = __half22float2(*(const __half2*)&hh.x);
        float2 f1 = __half22float2(*(const __half2*)&hh.y);
        ax += w0 * f0.x; ay += w0 * f0.y; az += w0 * f1.x; aw += w0 * f1.y;
        wsum += w0;
    }

    float inv = 1.0f / wsum;
    float4 v;
    v.x = ax * inv; v.y = ay * inv; v.z = az * inv; v.w = aw * inv;
    if (mode == 0) {
        v.x = (v.x > 0.f) ? v.x : expm1f(v.x);
        v.y = (v.y > 0.f) ? v.y : expm1f(v.y);
        v.z = (v.z > 0.f) ? v.z : expm1f(v.z);
        v.w = (v.w > 0.f) ? v.w : expm1f(v.w);
    } else {
        float4 sk = *(const float4*)(skip + (size_t)gwid * F + lane * 4);
        v.x += sk.x; v.y += sk.y; v.z += sk.z; v.w += sk.w;
    }
    *(float4*)(out + (size_t)gwid * F + lane * 4) = v;
}

// ---------------- launch ----------------
extern "C" void kernel_launch(void* const* d_in, const int* in_sizes, int n_in,
                              void* d_out, int out_size) {
    const float* x    = (const float*)d_in[0];
    const int*   eidx = (const int*)  d_in[1];
    const float* ev   = (const float*)d_in[2];
    const float* encW = (const float*)d_in[3];
    const float* encb = (const float*)d_in[4];
    const float* Wst  = (const float*)d_in[5];
    const float* ast  = (const float*)d_in[6];
    float* out = (float*)d_out;

    int N = in_sizes[0] / F;
    int E = in_sizes[2];
    const int* row  = eidx;
    const int* colp = eidx + E;

    float *xc, *asrc, *adst;
    __half *h16, *Bh;
    int *cnt, *excl, *bsum, *offs, *cursor;
    int2* ecomb;
    cudaGetSymbolAddress((void**)&xc,     g_xc);
    cudaGetSymbolAddress((void**)&h16,    g_h16);
    cudaGetSymbolAddress((void**)&asrc,   g_asrc);
    cudaGetSymbolAddress((void**)&adst,   g_adst);
    cudaGetSymbolAddress((void**)&cnt,    g_cnt);
    cudaGetSymbolAddress((void**)&excl,   g_excl);
    cudaGetSymbolAddress((void**)&bsum,   g_bsum);
    cudaGetSymbolAddress((void**)&offs,   g_offs);
    cudaGetSymbolAddress((void**)&cursor, g_cursor);
    cudaGetSymbolAddress((void**)&ecomb,  g_ecomb);
    cudaGetSymbolAddress((void**)&Bh,     g_Bh);

    static cudaStream_t s2 = nullptr;
    static cudaEvent_t evFork = nullptr, evJoin = nullptr;
    static int init_done = 0;
    if (!init_done) {
        cudaFuncSetAttribute(mma_gemm_kernel,
                             cudaFuncAttributeMaxDynamicSharedMemorySize, SMEM_TOT);
        cudaStreamCreateWithFlags(&s2, cudaStreamNonBlocking);
        cudaEventCreateWithFlags(&evFork, cudaEventDisableTiming);
        cudaEventCreateWithFlags(&evJoin, cudaEventDisableTiming);
        init_done = 1;
    }

    const int TB = 256;
    int num_tiles = (N + 63) / 64;
    int gemm_grid = (num_tiles < GEMM_GRID) ? num_tiles : GEMM_GRID;
    int edge_blocks = (N * 32 + TB - 1) / TB;
    int scan_blocks = (N + SCAN_B - 1) / SCAN_B;

    // ---- fork: CSR chain on s2, GEMM chain on the main/capture stream ----
    cudaEventRecord(evFork, 0);
    cudaStreamWaitEvent(s2, evFork, 0);

    // CSR chain (stream s2) — independent of all GEMM work
    zero_cnt_kernel<<<(N + TB - 1) / TB, TB, 0, s2>>>(cnt, N);
    hist_kernel<<<(E + TB - 1) / TB, TB, 0, s2>>>(row, cnt, E);
    blockscan_kernel<<<scan_blocks, SCAN_B, 0, s2>>>(cnt, excl, bsum, N);
    scan_apply_kernel<<<1, SCAN_B, 0, s2>>>(bsum, excl, offs, cursor, scan_blocks, N, E);
    scatter_kernel<<<(E + TB - 1) / TB, TB, 0, s2>>>(row, colp, ev, cursor, ecomb, E);
    cudaEventRecord(evJoin, s2);

    // GEMM chain (main stream)
    prepB_kernel<<<(3 * F * STR + TB - 1) / TB, TB>>>(encW, Wst);
    // encoder: xc = x @ enc_W + enc_b (f32 out)
    mma_gemm_kernel<<<gemm_grid, 256, SMEM_TOT>>>(x, Bh, encb, xc,
                                                  nullptr, nullptr, nullptr,
                                                  nullptr, N);

    for (int ell = 0; ell < 2; ell++) {
        const float* al = ast + ell * H * 2 * DH;
        const __half* bh = Bh + (1 + ell) * F * STR;

        // h16 = xc @ W (fp16 out), fused asrc/adst
        mma_gemm_kernel<<<gemm_grid, 256, SMEM_TOT>>>(xc, bh, nullptr, nullptr,
                                                      h16, al, asrc, adst, N);

        if (ell == 0) {
            // join: edge kernel needs the CSR arrays from s2
            cudaStreamWaitEvent(0, evJoin, 0);
            edge_csr_kernel<<<edge_blocks, TB>>>(offs, ecomb, asrc, adst, h16,
                                                 nullptr, xc, N, 0);
        } else {
            edge_csr_kernel<<<edge_blocks, TB>>>(offs, ecomb, asrc, adst, h16,
                                                 xc, out, N, 1);
        }
    }
}